// round 15
// baseline (speedup 1.0000x reference)
#include <cuda_runtime.h>
#include <cuda_fp16.h>
#include <cstdint>
#include <math.h>

// Problem constants
#define BB      4
#define LL      4096
#define DM      1024
#define DI      2048
#define DSTATE  64
#define HD      64
#define NH      32
#define CONVD   2176        // DI + 2*DSTATE
#define DIP     4256        // 2*DI + 2*DSTATE + NH
#define DFF     4096
#define MM      (BB*LL)     // 16384 rows
#define NCHUNK  16
#define LC      256         // LL / NCHUNK

// ---------------- scratch (static device globals; no allocs allowed) --------
__device__ __half g_ln1[MM*DM];
__device__ float  g_zx [MM*DIP];
__device__ float  g_xbc[MM*CONVD];
__device__ float  g_dt [MM*NH];
__device__ __half g_y  [MM*DI];
__device__ float  g_x2 [MM*DM];
__device__ __half g_ln2[MM*DM];
__device__ __half g_mlp[MM*DFF];
// chunked-scan buffers
__device__ float  g_hloc[BB*NH*NCHUNK*HD*DSTATE];
__device__ float  g_hini[BB*NH*NCHUNK*HD*DSTATE];
__device__ float  g_sdt [BB*NH*NCHUNK];
// fp16 weights (contiguous regions)
#define WOFF_INPROJ  0
#define WOFF_OUTPROJ (DIP*DM)
#define WOFF_FC      (WOFF_OUTPROJ + DM*DI)
#define WOFF_PROJ    (WOFF_FC + DFF*DM)
#define WTOTAL       (WOFF_PROJ + DM*DFF)
__device__ __half g_wh[WTOTAL];

// =================== helpers ===================
__device__ __forceinline__ void cp16(uint32_t dst, const void* src, uint32_t sz){
    asm volatile("cp.async.cg.shared.global [%0], [%1], 16, %2;" :: "r"(dst), "l"(src), "r"(sz));
}
__device__ __forceinline__ uint32_t smem_u32(const void* p){
    uint32_t a;
    asm("{ .reg .u64 t; cvta.to.shared.u64 t, %1; cvt.u32.u64 %0, t; }" : "=r"(a) : "l"(p));
    return a;
}
__device__ __forceinline__ void mma16816(float c[4], const uint32_t a[4], const uint32_t b[2]){
    asm volatile("mma.sync.aligned.m16n8k16.row.col.f32.f16.f16.f32 "
        "{%0,%1,%2,%3}, {%4,%5,%6,%7}, {%8,%9}, {%0,%1,%2,%3};"
        : "+f"(c[0]), "+f"(c[1]), "+f"(c[2]), "+f"(c[3])
        : "r"(a[0]), "r"(a[1]), "r"(a[2]), "r"(a[3]), "r"(b[0]), "r"(b[1]));
}
#define LDSM4(r0,r1,r2,r3,addr) \
    asm volatile("ldmatrix.sync.aligned.m8n8.x4.shared.b16 {%0,%1,%2,%3}, [%4];" \
        : "=r"(r0), "=r"(r1), "=r"(r2), "=r"(r3) : "r"(addr))
// packed f32x2 (Blackwell FFMA2 path)
#define PK2(out, lo, hi)  asm("mov.b64 %0, {%1, %2};" : "=l"(out) : "f"(lo), "f"(hi))
#define UPK2(lo, hi, in)  asm("mov.b64 {%0, %1}, %2;" : "=f"(lo), "=f"(hi) : "l"(in))
#define MUL2(d, a, b)     asm("mul.rn.f32x2 %0, %1, %2;" : "=l"(d) : "l"(a), "l"(b))
#define FMA2(d, a, b, c)  asm("fma.rn.f32x2 %0, %1, %2, %3;" : "=l"(d) : "l"(a), "l"(b), "l"(c))

// =================== fp16 mma.sync GEMM (ldmatrix, 4-stage pipeline) =======
// C[M,N] = A[M,K] * W[N,K]^T (+epilogue). 128x128 CTA tile, BK=32,
// 4 warps of 64x64, 4-stage cp.async (prefetch distance 3), ldmatrix.x4.
// Smem rows pitch 20 uint32 (80B): every 8-lane LDSM phase hits 32 banks.
// EPI: 0 none(f32 out), 1 bias+gelu(half out), 2 +resid(f32), 3 +bias+resid(f32)
#define GPITCH 20
#define GROWB  (GPITCH*4)                        // 80 bytes per row
#define GSTAGE_U32 (2*128*GPITCH)
#define GSTAGE_BYTES (GSTAGE_U32*4)              // 20480
#define GSTAGES 4
#define GEMM_DYNSMEM (GSTAGES*GSTAGE_BYTES)      // 81920

template<int EPI>
__global__ __launch_bounds__(128, 2)
void tc_gemm(const __half* __restrict__ Ap, const __half* __restrict__ Wp,
             const float* __restrict__ bias, const float* __restrict__ resid,
             void* __restrict__ Cv, int M, int N, int K)
{
    extern __shared__ uint32_t smu[];
    uint32_t smem_base = smem_u32(smu);
    int tid  = threadIdx.x;
    int wid  = tid >> 5;
    int lane = tid & 31;
    int g    = lane >> 2;
    int t4   = lane & 3;
    int wm   = (wid & 1) * 64;
    int wn   = (wid >> 1) * 64;

    int m0 = blockIdx.y * 128;
    int n0 = blockIdx.x * 128;
    int NC = K >> 5;

    uint32_t a_off = (uint32_t)((wm + (lane & 7) + ((lane >> 3) & 1) * 8) * GROWB
                                + (lane >> 4) * 16);
    uint32_t b_off = (uint32_t)((wn + (lane & 7) + (lane >> 4) * 8) * GROWB
                                + ((lane >> 3) & 1) * 16);

    float acc[4][8][4];
    #pragma unroll
    for (int mi = 0; mi < 4; mi++)
        #pragma unroll
        for (int ni = 0; ni < 8; ni++)
            #pragma unroll
            for (int r = 0; r < 4; r++) acc[mi][ni][r] = 0.f;

    auto load_chunk = [&](int c){
        uint32_t sb = smem_base + (uint32_t)(c & (GSTAGES-1)) * GSTAGE_BYTES;
        int k0 = c << 5;
        #pragma unroll
        for (int i = 0; i < 4; i++) {
            int gr = i*128 + tid;
            int r = gr >> 2, c16 = gr & 3;
            cp16(sb + (uint32_t)(r*GROWB + c16*16),
                 Ap + (size_t)(m0 + r)*K + k0 + c16*8, 16u);
        }
        #pragma unroll
        for (int i = 0; i < 4; i++) {
            int gr = i*128 + tid;
            int r = gr >> 2, c16 = gr & 3;
            int nr = n0 + r;
            uint32_t sz = (nr < N) ? 16u : 0u;
            cp16(sb + (uint32_t)(128*GROWB) + (uint32_t)(r*GROWB + c16*16),
                 Wp + (size_t)(nr < N ? nr : 0)*K + k0 + c16*8, sz);
        }
        asm volatile("cp.async.commit_group;" ::: "memory");
    };

    load_chunk(0);
    if (NC > 1) load_chunk(1);
    if (NC > 2) load_chunk(2);

    for (int c = 0; c < NC; c++) {
        int rem = NC - 1 - c;     // groups issued beyond c
        if (rem >= 2)      { asm volatile("cp.async.wait_group 2;" ::: "memory"); }
        else if (rem == 1) { asm volatile("cp.async.wait_group 1;" ::: "memory"); }
        else               { asm volatile("cp.async.wait_group 0;" ::: "memory"); }
        __syncthreads();
        if (c + 3 < NC) load_chunk(c + 3);   // stage freed by compute(c-1)

        uint32_t sA = smem_base + (uint32_t)(c & (GSTAGES-1)) * GSTAGE_BYTES;
        uint32_t sB = sA + 128*GROWB;
        #pragma unroll
        for (int ks = 0; ks < 2; ks++) {
            uint32_t ks_off = (uint32_t)ks * 32;
            uint32_t a[4][4], b[8][2];
            #pragma unroll
            for (int mi = 0; mi < 4; mi++)
                LDSM4(a[mi][0], a[mi][1], a[mi][2], a[mi][3],
                      sA + a_off + (uint32_t)mi*(16*GROWB) + ks_off);
            #pragma unroll
            for (int pr = 0; pr < 4; pr++)
                LDSM4(b[2*pr][0], b[2*pr][1], b[2*pr+1][0], b[2*pr+1][1],
                      sB + b_off + (uint32_t)pr*(16*GROWB) + ks_off);
            #pragma unroll
            for (int mi = 0; mi < 4; mi++)
                #pragma unroll
                for (int ni = 0; ni < 8; ni++)
                    mma16816(acc[mi][ni], a[mi], b[ni]);
        }
    }

    float*  Cf = (float*)Cv;
    __half* Ch = (__half*)Cv;
    #pragma unroll
    for (int mi = 0; mi < 4; mi++) {
        int r0 = m0 + wm + mi*16 + g;
        #pragma unroll
        for (int ni = 0; ni < 8; ni++) {
            int cc = n0 + wn + ni*8 + t4*2;
            #pragma unroll
            for (int half_ = 0; half_ < 2; half_++) {
                int row = r0 + half_*8;
                float v0 = acc[mi][ni][half_*2 + 0];
                float v1 = acc[mi][ni][half_*2 + 1];
                if (cc + 1 < N) {
                    if (EPI == 1) {
                        v0 += bias[cc];   v1 += bias[cc+1];
                        v0 = 0.5f*v0*(1.0f + erff(v0*0.70710678118654752f));
                        v1 = 0.5f*v1*(1.0f + erff(v1*0.70710678118654752f));
                        *(__half2*)&Ch[(size_t)row*N + cc] = __floats2half2_rn(v0, v1);
                    } else {
                        if (EPI == 2) { v0 += resid[(size_t)row*N + cc];
                                        v1 += resid[(size_t)row*N + cc + 1]; }
                        if (EPI == 3) { v0 += bias[cc]   + resid[(size_t)row*N + cc];
                                        v1 += bias[cc+1] + resid[(size_t)row*N + cc + 1]; }
                        *(float2*)&Cf[(size_t)row*N + cc] = make_float2(v0, v1);
                    }
                } else if (cc < N) {
                    float v = v0;
                    if (EPI == 1) {
                        v += bias[cc];
                        v = 0.5f*v*(1.0f + erff(v*0.70710678118654752f));
                        Ch[(size_t)row*N + cc] = __float2half_rn(v);
                    } else {
                        if (EPI == 2) v += resid[(size_t)row*N + cc];
                        if (EPI == 3) v += bias[cc] + resid[(size_t)row*N + cc];
                        Cf[(size_t)row*N + cc] = v;
                    }
                }
            }
        }
    }
}

// =================== block reduction ===================
__device__ __forceinline__ float block_reduce_sum(float v) {
    __shared__ float sm[32];
    __shared__ float total;
    int lane = threadIdx.x & 31;
    int wid  = threadIdx.x >> 5;
    #pragma unroll
    for (int o = 16; o > 0; o >>= 1) v += __shfl_xor_sync(0xffffffffu, v, o);
    if (lane == 0) sm[wid] = v;
    __syncthreads();
    int nw = blockDim.x >> 5;
    v = (threadIdx.x < nw) ? sm[threadIdx.x] : 0.0f;
    if (wid == 0) {
        #pragma unroll
        for (int o = 16; o > 0; o >>= 1) v += __shfl_xor_sync(0xffffffffu, v, o);
        if (lane == 0) total = v;
    }
    __syncthreads();
    float r = total;
    __syncthreads();
    return r;
}

// ---------------- layernorm (float4 in, half out) ----------------
__global__ void ln_kernel(const float* __restrict__ x,
                          const float* __restrict__ w,
                          const float* __restrict__ b,
                          __half* __restrict__ out) {
    size_t base = (size_t)blockIdx.x * DM;
    int c0 = threadIdx.x * 4;
    float4 v = *(const float4*)&x[base + c0];
    float s = v.x + v.y + v.z + v.w;
    float mean = block_reduce_sum(s) * (1.0f/DM);
    float dx = v.x-mean, dy = v.y-mean, dz = v.z-mean, dw = v.w-mean;
    float var = block_reduce_sum(dx*dx + dy*dy + dz*dz + dw*dw) * (1.0f/DM);
    float rstd = rsqrtf(var + 1e-5f);
    float4 wv = *(const float4*)&w[c0];
    float4 bv = *(const float4*)&b[c0];
    __half2 o0 = __floats2half2_rn(dx*rstd*wv.x + bv.x, dy*rstd*wv.y + bv.y);
    __half2 o1 = __floats2half2_rn(dz*rstd*wv.z + bv.z, dw*rstd*wv.w + bv.w);
    uint2 o; o.x = *(uint32_t*)&o0; o.y = *(uint32_t*)&o1;
    *(uint2*)&out[base + c0] = o;
}

// ---------------- merged fp16 weight conversion (one launch) --------------
#define N4_INPROJ  (DIP*DM/4)
#define N4_OUTPROJ (DM*DI/4)
#define N4_FC      (DFF*DM/4)
#define N4_PROJ    (DM*DFF/4)
#define N4_TOTAL   (N4_INPROJ + N4_OUTPROJ + N4_FC + N4_PROJ)
__global__ void cvtw_all_kernel(const float4* __restrict__ w0,
                                const float4* __restrict__ w1,
                                const float4* __restrict__ w2,
                                const float4* __restrict__ w3,
                                uint2* __restrict__ d) {
    int i = blockIdx.x * blockDim.x + threadIdx.x;
    if (i >= N4_TOTAL) return;
    float4 v;
    if      (i < N4_INPROJ)                        v = w0[i];
    else if (i < N4_INPROJ + N4_OUTPROJ)           v = w1[i - N4_INPROJ];
    else if (i < N4_INPROJ + N4_OUTPROJ + N4_FC)   v = w2[i - N4_INPROJ - N4_OUTPROJ];
    else                                           v = w3[i - N4_INPROJ - N4_OUTPROJ - N4_FC];
    __half2 h0 = __floats2half2_rn(v.x, v.y);
    __half2 h1 = __floats2half2_rn(v.z, v.w);
    uint2 o; o.x = *(uint32_t*)&h0; o.y = *(uint32_t*)&h1;
    d[i] = o;
}

// ---------------- dt = softplus(dt_raw + dt_bias) ----------------
__global__ void dt_kernel(const float* __restrict__ dt_bias) {
    int idx = blockIdx.x * blockDim.x + threadIdx.x;
    if (idx >= MM*NH) return;
    int h   = idx & (NH-1);
    int row = idx >> 5;
    float v = g_zx[(size_t)row*DIP + (2*DI + 2*DSTATE) + h] + dt_bias[h];
    g_dt[idx] = (v > 20.0f) ? v : log1pf(expf(v));
}

// ---------------- depthwise causal conv(4) + silu (float4 over c) ---------
__global__ void conv_kernel(const float* __restrict__ conv_w,
                            const float* __restrict__ conv_b) {
    int idx = blockIdx.x * blockDim.x + threadIdx.x;
    if (idx >= MM*(CONVD/4)) return;
    int c4  = (idx % (CONVD/4)) * 4;
    int row = idx / (CONVD/4);
    int l   = row & (LL-1);
    float4 acc = *(const float4*)&conv_b[c4];
    float4 w0 = *(const float4*)&conv_w[(c4+0)*4];
    float4 w1 = *(const float4*)&conv_w[(c4+1)*4];
    float4 w2 = *(const float4*)&conv_w[(c4+2)*4];
    float4 w3 = *(const float4*)&conv_w[(c4+3)*4];
    float wk0[4] = {w0.x, w0.y, w0.z, w0.w};
    float wk1[4] = {w1.x, w1.y, w1.z, w1.w};
    float wk2[4] = {w2.x, w2.y, w2.z, w2.w};
    float wk3[4] = {w3.x, w3.y, w3.z, w3.w};
    #pragma unroll
    for (int k = 0; k < 4; k++) {
        int ls = l - 3 + k;
        if (ls >= 0) {
            float4 xv = *(const float4*)&g_zx[(size_t)(row-3+k)*DIP + DI + c4];
            acc.x = fmaf(wk0[k], xv.x, acc.x);
            acc.y = fmaf(wk1[k], xv.y, acc.y);
            acc.z = fmaf(wk2[k], xv.z, acc.z);
            acc.w = fmaf(wk3[k], xv.w, acc.w);
        }
    }
    acc.x /= (1.0f + expf(-acc.x));
    acc.y /= (1.0f + expf(-acc.y));
    acc.z /= (1.0f + expf(-acc.z));
    acc.w /= (1.0f + expf(-acc.w));
    *(float4*)&g_xbc[(size_t)row*CONVD + c4] = acc;
}

// ---------------- chunked SSM scan ----------------
__global__ __launch_bounds__(64)
void scan1_kernel(const float* __restrict__ A_log) {
    int chunk = blockIdx.x;
    int bh    = blockIdx.y;
    int b = bh >> 5, h = bh & 31;
    int p = threadIdx.x;
    float A = -expf(A_log[h]);
    unsigned long long hs2[DSTATE/2];
    #pragma unroll
    for (int n = 0; n < DSTATE/2; n++) hs2[n] = 0ull;
    float sdt = 0.f;

    __shared__ float Bsm[8][DSTATE];
    __shared__ float dts[8];
    const int xcol = h*HD + p;
    int rbase0 = b*LL + chunk*LC;

    for (int t0 = 0; t0 < LC; t0 += 8) {
        #pragma unroll
        for (int s = 0; s < 8; s++)
            Bsm[s][p] = g_xbc[(size_t)(rbase0 + t0 + s)*CONVD + DI + p];
        if (p < 8) dts[p] = g_dt[(size_t)(rbase0 + t0 + p)*NH + h];
        __syncthreads();
        #pragma unroll
        for (int s = 0; s < 8; s++) {
            int row   = rbase0 + t0 + s;
            float dtv = dts[s];
            sdt += dtv;
            float a   = expf(dtv * A);
            float xv  = g_xbc[(size_t)row*CONVD + xcol];
            float dtx = dtv * xv;
            unsigned long long a2, dtx2;
            PK2(a2, a, a);
            PK2(dtx2, dtx, dtx);
            #pragma unroll
            for (int n = 0; n < DSTATE; n += 4) {
                float4 Bv = *(const float4*)&Bsm[s][n];
                unsigned long long b01, b23, t01, t23;
                PK2(b01, Bv.x, Bv.y); PK2(b23, Bv.z, Bv.w);
                MUL2(t01, dtx2, b01);
                MUL2(t23, dtx2, b23);
                FMA2(hs2[n/2],   a2, hs2[n/2],   t01);
                FMA2(hs2[n/2+1], a2, hs2[n/2+1], t23);
            }
        }
        __syncthreads();
    }
    size_t base = ((size_t)(bh*NCHUNK + chunk)*HD + p)*DSTATE;
    #pragma unroll
    for (int n = 0; n < DSTATE; n += 4) {
        float4 o;
        UPK2(o.x, o.y, hs2[n/2]);
        UPK2(o.z, o.w, hs2[n/2+1]);
        *(float4*)&g_hloc[base + n] = o;
    }
    if (p == 0) g_sdt[bh*NCHUNK + chunk] = sdt;
}

__global__ __launch_bounds__(256)
void scan2_kernel(const float* __restrict__ A_log) {
    int bh = blockIdx.x;
    int h  = bh & 31;
    float A = -expf(A_log[h]);
    int p = threadIdx.x & 63;
    int q = threadIdx.x >> 6;
    float hr[16];
    #pragma unroll
    for (int j = 0; j < 16; j++) hr[j] = 0.f;
    for (int c = 0; c < NCHUNK; c++) {
        size_t base = ((size_t)(bh*NCHUNK + c)*HD + p)*DSTATE + q*16;
        #pragma unroll
        for (int j = 0; j < 16; j += 4)
            *(float4*)&g_hini[base + j] = make_float4(hr[j], hr[j+1], hr[j+2], hr[j+3]);
        float P = expf(A * g_sdt[bh*NCHUNK + c]);
        #pragma unroll
        for (int j = 0; j < 16; j += 4) {
            float4 hl = *(const float4*)&g_hloc[base + j];
            hr[j]   = fmaf(P, hr[j],   hl.x);
            hr[j+1] = fmaf(P, hr[j+1], hl.y);
            hr[j+2] = fmaf(P, hr[j+2], hl.z);
            hr[j+3] = fmaf(P, hr[j+3], hl.w);
        }
    }
}

__global__ __launch_bounds__(64)
void scan3_kernel(const float* __restrict__ A_log,
                  const float* __restrict__ D_param) {
    int chunk = blockIdx.x;
    int bh    = blockIdx.y;
    int b = bh >> 5, h = bh & 31;
    int p = threadIdx.x;
    float A  = -expf(A_log[h]);
    float Dp = D_param[h];
    unsigned long long hs2[DSTATE/2];
    {
        size_t base = ((size_t)(bh*NCHUNK + chunk)*HD + p)*DSTATE;
        #pragma unroll
        for (int n = 0; n < DSTATE; n += 4) {
            float4 hv = *(const float4*)&g_hini[base + n];
            PK2(hs2[n/2],   hv.x, hv.y);
            PK2(hs2[n/2+1], hv.z, hv.w);
        }
    }

    __shared__ float Bsm[8][DSTATE];
    __shared__ float Csm[8][DSTATE];
    __shared__ float dts[8];
    const int xcol = h*HD + p;
    int rbase0 = b*LL + chunk*LC;

    for (int t0 = 0; t0 < LC; t0 += 8) {
        #pragma unroll
        for (int s = 0; s < 8; s++) {
            size_t rb = (size_t)(rbase0 + t0 + s) * CONVD;
            Bsm[s][p] = g_xbc[rb + DI + p];
            Csm[s][p] = g_xbc[rb + DI + DSTATE + p];
        }
        if (p < 8) dts[p] = g_dt[(size_t)(rbase0 + t0 + p)*NH + h];
        __syncthreads();
        #pragma unroll
        for (int s = 0; s < 8; s++) {
            int row   = rbase0 + t0 + s;
            float dtv = dts[s];
            float a   = expf(dtv * A);
            float xv  = g_xbc[(size_t)row*CONVD + xcol];
            float dtx = dtv * xv;
            unsigned long long a2, dtx2, acc2 = 0ull;
            PK2(a2, a, a);
            PK2(dtx2, dtx, dtx);
            #pragma unroll
            for (int n = 0; n < DSTATE; n += 4) {
                float4 Bv = *(const float4*)&Bsm[s][n];
                float4 Cv = *(const float4*)&Csm[s][n];
                unsigned long long b01, b23, c01, c23, t01, t23;
                PK2(b01, Bv.x, Bv.y); PK2(b23, Bv.z, Bv.w);
                PK2(c01, Cv.x, Cv.y); PK2(c23, Cv.z, Cv.w);
                MUL2(t01, dtx2, b01);
                MUL2(t23, dtx2, b23);
                FMA2(hs2[n/2],   a2, hs2[n/2],   t01);
                FMA2(hs2[n/2+1], a2, hs2[n/2+1], t23);
                FMA2(acc2, hs2[n/2],   c01, acc2);
                FMA2(acc2, hs2[n/2+1], c23, acc2);
            }
            float alo, ahi;
            UPK2(alo, ahi, acc2);
            g_y[(size_t)row*DI + xcol] = __float2half_rn(alo + ahi + Dp*xv);
        }
        __syncthreads();
    }
}

// ---------------- y = rmsnorm(y * silu(z)) * norm_w (vectorized) ----------
__global__ void gate_rms_kernel(const float* __restrict__ norm_w) {
    size_t row = blockIdx.x;
    int c0 = threadIdx.x * 8;
    float zz[8];
    *(float4*)&zz[0] = *(const float4*)&g_zx[row*DIP + c0];
    *(float4*)&zz[4] = *(const float4*)&g_zx[row*DIP + c0 + 4];
    uint4 yu = *(const uint4*)&g_y[row*DI + c0];
    __half2 yh[4];
    yh[0] = *(__half2*)&yu.x; yh[1] = *(__half2*)&yu.y;
    yh[2] = *(__half2*)&yu.z; yh[3] = *(__half2*)&yu.w;
    float vals[8];
    float ss = 0.f;
    #pragma unroll
    for (int i = 0; i < 8; i++) {
        float z  = zz[i];
        float yv = (i & 1) ? __high2float(yh[i>>1]) : __low2float(yh[i>>1]);
        float gg = yv * (z / (1.0f + expf(-z)));
        vals[i] = gg;
        ss += gg*gg;
    }
    float ms = block_reduce_sum(ss) * (1.0f/DI);
    float r  = rsqrtf(ms + 1e-5f);
    float ww[8];
    *(float4*)&ww[0] = *(const float4*)&norm_w[c0];
    *(float4*)&ww[4] = *(const float4*)&norm_w[c0 + 4];
    uint4 o;
    __half2 oh[4];
    #pragma unroll
    for (int i = 0; i < 4; i++)
        oh[i] = __floats2half2_rn(vals[2*i] * r * ww[2*i], vals[2*i+1] * r * ww[2*i+1]);
    o.x = *(uint32_t*)&oh[0]; o.y = *(uint32_t*)&oh[1];
    o.z = *(uint32_t*)&oh[2]; o.w = *(uint32_t*)&oh[3];
    *(uint4*)&g_y[row*DI + c0] = o;
}

// ---------------- host launch ----------------
extern "C" void kernel_launch(void* const* d_in, const int* in_sizes, int n_in,
                              void* d_out, int out_size)
{
    const float* x         = (const float*)d_in[0];
    const float* ln1_w     = (const float*)d_in[1];
    const float* ln1_b     = (const float*)d_in[2];
    const float* ln2_w     = (const float*)d_in[3];
    const float* ln2_b     = (const float*)d_in[4];
    const float* in_proj_w = (const float*)d_in[5];
    const float* conv_w    = (const float*)d_in[6];
    const float* conv_b    = (const float*)d_in[7];
    const float* dt_bias   = (const float*)d_in[8];
    const float* A_log     = (const float*)d_in[9];
    const float* D_param   = (const float*)d_in[10];
    const float* norm_w    = (const float*)d_in[11];
    const float* out_proj_w= (const float*)d_in[12];
    const float* fc_w      = (const float*)d_in[13];
    const float* fc_b      = (const float*)d_in[14];
    const float* proj_w    = (const float*)d_in[15];
    const float* proj_b    = (const float*)d_in[16];
    float* out = (float*)d_out;

    __half *p_ln1, *p_y, *p_ln2, *p_mlp, *p_wh;
    float  *p_zx, *p_x2;
    cudaGetSymbolAddress((void**)&p_ln1, g_ln1);
    cudaGetSymbolAddress((void**)&p_zx,  g_zx);
    cudaGetSymbolAddress((void**)&p_y,   g_y);
    cudaGetSymbolAddress((void**)&p_x2,  g_x2);
    cudaGetSymbolAddress((void**)&p_ln2, g_ln2);
    cudaGetSymbolAddress((void**)&p_mlp, g_mlp);
    cudaGetSymbolAddress((void**)&p_wh,  g_wh);

    cudaFuncSetAttribute(tc_gemm<0>, cudaFuncAttributeMaxDynamicSharedMemorySize, GEMM_DYNSMEM);
    cudaFuncSetAttribute(tc_gemm<1>, cudaFuncAttributeMaxDynamicSharedMemorySize, GEMM_DYNSMEM);
    cudaFuncSetAttribute(tc_gemm<2>, cudaFuncAttributeMaxDynamicSharedMemorySize, GEMM_DYNSMEM);
    cudaFuncSetAttribute(tc_gemm<3>, cudaFuncAttributeMaxDynamicSharedMemorySize, GEMM_DYNSMEM);

    // 0. fp16-convert all weights (one launch)
    cvtw_all_kernel<<<(N4_TOTAL + 255)/256, 256>>>(
        (const float4*)in_proj_w, (const float4*)out_proj_w,
        (const float4*)fc_w, (const float4*)proj_w, (uint2*)p_wh);

    // 1. LN1 (half out)
    ln_kernel<<<MM, 256>>>(x, ln1_w, ln1_b, p_ln1);
    // 2. in_proj -> g_zx (f32)
    {
        dim3 grid((DIP + 127)/128, MM/128);
        tc_gemm<0><<<grid, 128, GEMM_DYNSMEM>>>(p_ln1, p_wh + WOFF_INPROJ,
                                                nullptr, nullptr, p_zx, MM, DIP, DM);
    }
    // 3. dt
    dt_kernel<<<(MM*NH + 255)/256, 256>>>(dt_bias);
    // 4. conv + silu (float4)
    conv_kernel<<<(MM*(CONVD/4) + 255)/256, 256>>>(conv_w, conv_b);
    // 5. chunked SSM scan
    {
        dim3 gs(NCHUNK, BB*NH);
        scan1_kernel<<<gs, 64>>>(A_log);
        scan2_kernel<<<BB*NH, 256>>>(A_log);
        scan3_kernel<<<gs, 64>>>(A_log, D_param);
    }
    // 6. gate + rmsnorm (half in/out)
    gate_rms_kernel<<<MM, 256>>>(norm_w);
    // 7. out_proj + residual(x) -> g_x2 (f32)
    {
        dim3 grid(DM/128, MM/128);
        tc_gemm<2><<<grid, 128, GEMM_DYNSMEM>>>(p_y, p_wh + WOFF_OUTPROJ,
                                                nullptr, x, p_x2, MM, DM, DI);
    }
    // 8. LN2 (half out)
    ln_kernel<<<MM, 256>>>(p_x2, ln2_w, ln2_b, p_ln2);
    // 9. fc + bias + gelu -> g_mlp (half out)
    {
        dim3 grid(DFF/128, MM/128);
        tc_gemm<1><<<grid, 128, GEMM_DYNSMEM>>>(p_ln2, p_wh + WOFF_FC,
                                                fc_b, nullptr, p_mlp, MM, DFF, DM);
    }
    // 10. proj + bias + residual(g_x2) -> out (f32)
    {
        dim3 grid(DM/128, MM/128);
        tc_gemm<3><<<grid, 128, GEMM_DYNSMEM>>>(p_mlp, p_wh + WOFF_PROJ,
                                                proj_b, p_x2, out, MM, DM, DFF);
    }
}

// round 16
// speedup vs baseline: 1.6554x; 1.6554x over previous
#include <cuda_runtime.h>
#include <cuda_fp16.h>
#include <cstdint>
#include <math.h>

// Problem constants
#define BB      4
#define LL      4096
#define DM      1024
#define DI      2048
#define DSTATE  64
#define HD      64
#define NH      32
#define CONVD   2176        // DI + 2*DSTATE
#define DIP     4256        // 2*DI + 2*DSTATE + NH
#define DFF     4096
#define MM      (BB*LL)     // 16384 rows
#define NCHUNK  16
#define LC      256         // LL / NCHUNK

// ---------------- scratch (static device globals; no allocs allowed) --------
__device__ __half g_ln1[MM*DM];
__device__ float  g_zx [MM*DIP];
__device__ float  g_xbc[MM*CONVD];
__device__ float  g_dt [MM*NH];
__device__ __half g_y  [MM*DI];
__device__ float  g_x2 [MM*DM];
__device__ __half g_ln2[MM*DM];
__device__ __half g_mlp[MM*DFF];
// chunked-scan buffers
__device__ float  g_hloc[BB*NH*NCHUNK*HD*DSTATE];
__device__ float  g_hini[BB*NH*NCHUNK*HD*DSTATE];
__device__ float  g_sdt [BB*NH*NCHUNK];
// fp16 weights (contiguous regions)
#define WOFF_INPROJ  0
#define WOFF_OUTPROJ (DIP*DM)
#define WOFF_FC      (WOFF_OUTPROJ + DM*DI)
#define WOFF_PROJ    (WOFF_FC + DFF*DM)
#define WTOTAL       (WOFF_PROJ + DM*DFF)
__device__ __half g_wh[WTOTAL];

// =================== helpers ===================
__device__ __forceinline__ void cp16(uint32_t dst, const void* src, uint32_t sz){
    asm volatile("cp.async.cg.shared.global [%0], [%1], 16, %2;" :: "r"(dst), "l"(src), "r"(sz));
}
__device__ __forceinline__ uint32_t smem_u32(const void* p){
    uint32_t a;
    asm("{ .reg .u64 t; cvta.to.shared.u64 t, %1; cvt.u32.u64 %0, t; }" : "=r"(a) : "l"(p));
    return a;
}
__device__ __forceinline__ void mma16816(float c[4], const uint32_t a[4], const uint32_t b[2]){
    asm volatile("mma.sync.aligned.m16n8k16.row.col.f32.f16.f16.f32 "
        "{%0,%1,%2,%3}, {%4,%5,%6,%7}, {%8,%9}, {%0,%1,%2,%3};"
        : "+f"(c[0]), "+f"(c[1]), "+f"(c[2]), "+f"(c[3])
        : "r"(a[0]), "r"(a[1]), "r"(a[2]), "r"(a[3]), "r"(b[0]), "r"(b[1]));
}
#define LDSM4(r0,r1,r2,r3,addr) \
    asm volatile("ldmatrix.sync.aligned.m8n8.x4.shared.b16 {%0,%1,%2,%3}, [%4];" \
        : "=r"(r0), "=r"(r1), "=r"(r2), "=r"(r3) : "r"(addr))
// packed f32x2 (Blackwell FFMA2 path)
#define PK2(out, lo, hi)  asm("mov.b64 %0, {%1, %2};" : "=l"(out) : "f"(lo), "f"(hi))
#define UPK2(lo, hi, in)  asm("mov.b64 {%0, %1}, %2;" : "=f"(lo), "=f"(hi) : "l"(in))
#define MUL2(d, a, b)     asm("mul.rn.f32x2 %0, %1, %2;" : "=l"(d) : "l"(a), "l"(b))
#define FMA2(d, a, b, c)  asm("fma.rn.f32x2 %0, %1, %2, %3;" : "=l"(d) : "l"(a), "l"(b), "l"(c))

// =================== fp16 mma.sync GEMM (R14 config: 3-stage, dist 2) ======
// C[M,N] = A[M,K] * W[N,K]^T (+epilogue). 128x128 CTA tile, BK=32,
// 4 warps of 64x64, 3-stage cp.async (prefetch distance 2), ldmatrix.x4.
// Smem rows pitch 20 uint32 (80B): every 8-lane LDSM phase hits 32 banks.
// EPI: 0 none(f32 out), 1 bias+gelu(half out), 2 +resid(f32), 3 +bias+resid(f32)
#define GPITCH 20
#define GROWB  (GPITCH*4)                        // 80 bytes per row
#define GSTAGE_U32 (2*128*GPITCH)
#define GSTAGE_BYTES (GSTAGE_U32*4)              // 20480
#define GSTAGES 3
#define GEMM_DYNSMEM (GSTAGES*GSTAGE_BYTES)      // 61440

template<int EPI>
__global__ __launch_bounds__(128, 2)
void tc_gemm(const __half* __restrict__ Ap, const __half* __restrict__ Wp,
             const float* __restrict__ bias, const float* __restrict__ resid,
             void* __restrict__ Cv, int M, int N, int K)
{
    extern __shared__ uint32_t smu[];
    uint32_t smem_base = smem_u32(smu);
    int tid  = threadIdx.x;
    int wid  = tid >> 5;
    int lane = tid & 31;
    int g    = lane >> 2;
    int t4   = lane & 3;
    int wm   = (wid & 1) * 64;
    int wn   = (wid >> 1) * 64;

    int m0 = blockIdx.y * 128;
    int n0 = blockIdx.x * 128;
    int NC = K >> 5;

    uint32_t a_off = (uint32_t)((wm + (lane & 7) + ((lane >> 3) & 1) * 8) * GROWB
                                + (lane >> 4) * 16);
    uint32_t b_off = (uint32_t)((wn + (lane & 7) + (lane >> 4) * 8) * GROWB
                                + ((lane >> 3) & 1) * 16);

    float acc[4][8][4];
    #pragma unroll
    for (int mi = 0; mi < 4; mi++)
        #pragma unroll
        for (int ni = 0; ni < 8; ni++)
            #pragma unroll
            for (int r = 0; r < 4; r++) acc[mi][ni][r] = 0.f;

    auto load_chunk = [&](int c){
        uint32_t sb = smem_base + (uint32_t)(c % GSTAGES) * GSTAGE_BYTES;
        int k0 = c << 5;
        #pragma unroll
        for (int i = 0; i < 4; i++) {
            int gr = i*128 + tid;
            int r = gr >> 2, c16 = gr & 3;
            cp16(sb + (uint32_t)(r*GROWB + c16*16),
                 Ap + (size_t)(m0 + r)*K + k0 + c16*8, 16u);
        }
        #pragma unroll
        for (int i = 0; i < 4; i++) {
            int gr = i*128 + tid;
            int r = gr >> 2, c16 = gr & 3;
            int nr = n0 + r;
            uint32_t sz = (nr < N) ? 16u : 0u;
            cp16(sb + (uint32_t)(128*GROWB) + (uint32_t)(r*GROWB + c16*16),
                 Wp + (size_t)(nr < N ? nr : 0)*K + k0 + c16*8, sz);
        }
        asm volatile("cp.async.commit_group;" ::: "memory");
    };

    load_chunk(0);
    if (NC > 1) load_chunk(1);

    for (int c = 0; c < NC; c++) {
        if (c + 1 < NC) { asm volatile("cp.async.wait_group 1;" ::: "memory"); }
        else            { asm volatile("cp.async.wait_group 0;" ::: "memory"); }
        __syncthreads();
        if (c + 2 < NC) load_chunk(c + 2);

        uint32_t sA = smem_base + (uint32_t)(c % GSTAGES) * GSTAGE_BYTES;
        uint32_t sB = sA + 128*GROWB;
        #pragma unroll
        for (int ks = 0; ks < 2; ks++) {
            uint32_t ks_off = (uint32_t)ks * 32;
            uint32_t a[4][4], b[8][2];
            #pragma unroll
            for (int mi = 0; mi < 4; mi++)
                LDSM4(a[mi][0], a[mi][1], a[mi][2], a[mi][3],
                      sA + a_off + (uint32_t)mi*(16*GROWB) + ks_off);
            #pragma unroll
            for (int pr = 0; pr < 4; pr++)
                LDSM4(b[2*pr][0], b[2*pr][1], b[2*pr+1][0], b[2*pr+1][1],
                      sB + b_off + (uint32_t)pr*(16*GROWB) + ks_off);
            #pragma unroll
            for (int mi = 0; mi < 4; mi++)
                #pragma unroll
                for (int ni = 0; ni < 8; ni++)
                    mma16816(acc[mi][ni], a[mi], b[ni]);
        }
    }

    float*  Cf = (float*)Cv;
    __half* Ch = (__half*)Cv;
    #pragma unroll
    for (int mi = 0; mi < 4; mi++) {
        int r0 = m0 + wm + mi*16 + g;
        #pragma unroll
        for (int ni = 0; ni < 8; ni++) {
            int cc = n0 + wn + ni*8 + t4*2;
            #pragma unroll
            for (int half_ = 0; half_ < 2; half_++) {
                int row = r0 + half_*8;
                float v0 = acc[mi][ni][half_*2 + 0];
                float v1 = acc[mi][ni][half_*2 + 1];
                if (cc + 1 < N) {
                    if (EPI == 1) {
                        v0 += bias[cc];   v1 += bias[cc+1];
                        v0 = 0.5f*v0*(1.0f + erff(v0*0.70710678118654752f));
                        v1 = 0.5f*v1*(1.0f + erff(v1*0.70710678118654752f));
                        *(__half2*)&Ch[(size_t)row*N + cc] = __floats2half2_rn(v0, v1);
                    } else {
                        if (EPI == 2) { v0 += resid[(size_t)row*N + cc];
                                        v1 += resid[(size_t)row*N + cc + 1]; }
                        if (EPI == 3) { v0 += bias[cc]   + resid[(size_t)row*N + cc];
                                        v1 += bias[cc+1] + resid[(size_t)row*N + cc + 1]; }
                        *(float2*)&Cf[(size_t)row*N + cc] = make_float2(v0, v1);
                    }
                } else if (cc < N) {
                    float v = v0;
                    if (EPI == 1) {
                        v += bias[cc];
                        v = 0.5f*v*(1.0f + erff(v*0.70710678118654752f));
                        Ch[(size_t)row*N + cc] = __float2half_rn(v);
                    } else {
                        if (EPI == 2) v += resid[(size_t)row*N + cc];
                        if (EPI == 3) v += bias[cc] + resid[(size_t)row*N + cc];
                        Cf[(size_t)row*N + cc] = v;
                    }
                }
            }
        }
    }
}

// =================== block reduction ===================
__device__ __forceinline__ float block_reduce_sum(float v) {
    __shared__ float sm[32];
    __shared__ float total;
    int lane = threadIdx.x & 31;
    int wid  = threadIdx.x >> 5;
    #pragma unroll
    for (int o = 16; o > 0; o >>= 1) v += __shfl_xor_sync(0xffffffffu, v, o);
    if (lane == 0) sm[wid] = v;
    __syncthreads();
    int nw = blockDim.x >> 5;
    v = (threadIdx.x < nw) ? sm[threadIdx.x] : 0.0f;
    if (wid == 0) {
        #pragma unroll
        for (int o = 16; o > 0; o >>= 1) v += __shfl_xor_sync(0xffffffffu, v, o);
        if (lane == 0) total = v;
    }
    __syncthreads();
    float r = total;
    __syncthreads();
    return r;
}

// ---------------- layernorm (float4 in, half out) ----------------
__global__ void ln_kernel(const float* __restrict__ x,
                          const float* __restrict__ w,
                          const float* __restrict__ b,
                          __half* __restrict__ out) {
    size_t base = (size_t)blockIdx.x * DM;
    int c0 = threadIdx.x * 4;
    float4 v = *(const float4*)&x[base + c0];
    float s = v.x + v.y + v.z + v.w;
    float mean = block_reduce_sum(s) * (1.0f/DM);
    float dx = v.x-mean, dy = v.y-mean, dz = v.z-mean, dw = v.w-mean;
    float var = block_reduce_sum(dx*dx + dy*dy + dz*dz + dw*dw) * (1.0f/DM);
    float rstd = rsqrtf(var + 1e-5f);
    float4 wv = *(const float4*)&w[c0];
    float4 bv = *(const float4*)&b[c0];
    __half2 o0 = __floats2half2_rn(dx*rstd*wv.x + bv.x, dy*rstd*wv.y + bv.y);
    __half2 o1 = __floats2half2_rn(dz*rstd*wv.z + bv.z, dw*rstd*wv.w + bv.w);
    uint2 o; o.x = *(uint32_t*)&o0; o.y = *(uint32_t*)&o1;
    *(uint2*)&out[base + c0] = o;
}

// ---------------- merged fp16 weight conversion (one launch) --------------
#define N4_INPROJ  (DIP*DM/4)
#define N4_OUTPROJ (DM*DI/4)
#define N4_FC      (DFF*DM/4)
#define N4_PROJ    (DM*DFF/4)
#define N4_TOTAL   (N4_INPROJ + N4_OUTPROJ + N4_FC + N4_PROJ)
__global__ void cvtw_all_kernel(const float4* __restrict__ w0,
                                const float4* __restrict__ w1,
                                const float4* __restrict__ w2,
                                const float4* __restrict__ w3,
                                uint2* __restrict__ d) {
    int i = blockIdx.x * blockDim.x + threadIdx.x;
    if (i >= N4_TOTAL) return;
    float4 v;
    if      (i < N4_INPROJ)                        v = w0[i];
    else if (i < N4_INPROJ + N4_OUTPROJ)           v = w1[i - N4_INPROJ];
    else if (i < N4_INPROJ + N4_OUTPROJ + N4_FC)   v = w2[i - N4_INPROJ - N4_OUTPROJ];
    else                                           v = w3[i - N4_INPROJ - N4_OUTPROJ - N4_FC];
    __half2 h0 = __floats2half2_rn(v.x, v.y);
    __half2 h1 = __floats2half2_rn(v.z, v.w);
    uint2 o; o.x = *(uint32_t*)&h0; o.y = *(uint32_t*)&h1;
    d[i] = o;
}

// ---------------- depthwise causal conv(4)+silu, fused dt softplus --------
// idx < MM*(CONVD/4): conv over 4 channels (float4).
// idx >= that: softplus(dt_raw + dt_bias) for 4 heads (float4).
#define NCONV4 (MM*(CONVD/4))
#define NDT4   (MM*(NH/4))
__global__ void conv_dt_kernel(const float* __restrict__ conv_w,
                               const float* __restrict__ conv_b,
                               const float* __restrict__ dt_bias) {
    int idx = blockIdx.x * blockDim.x + threadIdx.x;
    if (idx < NCONV4) {
        int c4  = (idx % (CONVD/4)) * 4;
        int row = idx / (CONVD/4);
        int l   = row & (LL-1);
        float4 acc = *(const float4*)&conv_b[c4];
        float4 w0 = *(const float4*)&conv_w[(c4+0)*4];
        float4 w1 = *(const float4*)&conv_w[(c4+1)*4];
        float4 w2 = *(const float4*)&conv_w[(c4+2)*4];
        float4 w3 = *(const float4*)&conv_w[(c4+3)*4];
        float wk0[4] = {w0.x, w0.y, w0.z, w0.w};
        float wk1[4] = {w1.x, w1.y, w1.z, w1.w};
        float wk2[4] = {w2.x, w2.y, w2.z, w2.w};
        float wk3[4] = {w3.x, w3.y, w3.z, w3.w};
        #pragma unroll
        for (int k = 0; k < 4; k++) {
            int ls = l - 3 + k;
            if (ls >= 0) {
                float4 xv = *(const float4*)&g_zx[(size_t)(row-3+k)*DIP + DI + c4];
                acc.x = fmaf(wk0[k], xv.x, acc.x);
                acc.y = fmaf(wk1[k], xv.y, acc.y);
                acc.z = fmaf(wk2[k], xv.z, acc.z);
                acc.w = fmaf(wk3[k], xv.w, acc.w);
            }
        }
        acc.x /= (1.0f + expf(-acc.x));
        acc.y /= (1.0f + expf(-acc.y));
        acc.z /= (1.0f + expf(-acc.z));
        acc.w /= (1.0f + expf(-acc.w));
        *(float4*)&g_xbc[(size_t)row*CONVD + c4] = acc;
    } else if (idx < NCONV4 + NDT4) {
        int j   = idx - NCONV4;
        int h4  = (j % (NH/4)) * 4;
        int row = j / (NH/4);
        float4 v = *(const float4*)&g_zx[(size_t)row*DIP + 2*DI + 2*DSTATE + h4];
        float4 bv = *(const float4*)&dt_bias[h4];
        v.x += bv.x; v.y += bv.y; v.z += bv.z; v.w += bv.w;
        v.x = (v.x > 20.0f) ? v.x : log1pf(expf(v.x));
        v.y = (v.y > 20.0f) ? v.y : log1pf(expf(v.y));
        v.z = (v.z > 20.0f) ? v.z : log1pf(expf(v.z));
        v.w = (v.w > 20.0f) ? v.w : log1pf(expf(v.w));
        *(float4*)&g_dt[(size_t)row*NH + h4] = v;
    }
}

// ---------------- chunked SSM scan ----------------
__global__ __launch_bounds__(64)
void scan1_kernel(const float* __restrict__ A_log) {
    int chunk = blockIdx.x;
    int bh    = blockIdx.y;
    int b = bh >> 5, h = bh & 31;
    int p = threadIdx.x;
    float A = -expf(A_log[h]);
    unsigned long long hs2[DSTATE/2];
    #pragma unroll
    for (int n = 0; n < DSTATE/2; n++) hs2[n] = 0ull;
    float sdt = 0.f;

    __shared__ float Bsm[8][DSTATE];
    __shared__ float dts[8];
    const int xcol = h*HD + p;
    int rbase0 = b*LL + chunk*LC;

    for (int t0 = 0; t0 < LC; t0 += 8) {
        #pragma unroll
        for (int s = 0; s < 8; s++)
            Bsm[s][p] = g_xbc[(size_t)(rbase0 + t0 + s)*CONVD + DI + p];
        if (p < 8) dts[p] = g_dt[(size_t)(rbase0 + t0 + p)*NH + h];
        __syncthreads();
        #pragma unroll
        for (int s = 0; s < 8; s++) {
            int row   = rbase0 + t0 + s;
            float dtv = dts[s];
            sdt += dtv;
            float a   = expf(dtv * A);
            float xv  = g_xbc[(size_t)row*CONVD + xcol];
            float dtx = dtv * xv;
            unsigned long long a2, dtx2;
            PK2(a2, a, a);
            PK2(dtx2, dtx, dtx);
            #pragma unroll
            for (int n = 0; n < DSTATE; n += 4) {
                float4 Bv = *(const float4*)&Bsm[s][n];
                unsigned long long b01, b23, t01, t23;
                PK2(b01, Bv.x, Bv.y); PK2(b23, Bv.z, Bv.w);
                MUL2(t01, dtx2, b01);
                MUL2(t23, dtx2, b23);
                FMA2(hs2[n/2],   a2, hs2[n/2],   t01);
                FMA2(hs2[n/2+1], a2, hs2[n/2+1], t23);
            }
        }
        __syncthreads();
    }
    size_t base = ((size_t)(bh*NCHUNK + chunk)*HD + p)*DSTATE;
    #pragma unroll
    for (int n = 0; n < DSTATE; n += 4) {
        float4 o;
        UPK2(o.x, o.y, hs2[n/2]);
        UPK2(o.z, o.w, hs2[n/2+1]);
        *(float4*)&g_hloc[base + n] = o;
    }
    if (p == 0) g_sdt[bh*NCHUNK + chunk] = sdt;
}

__global__ __launch_bounds__(256)
void scan2_kernel(const float* __restrict__ A_log) {
    int bh = blockIdx.x;
    int h  = bh & 31;
    float A = -expf(A_log[h]);
    int p = threadIdx.x & 63;
    int q = threadIdx.x >> 6;
    float hr[16];
    #pragma unroll
    for (int j = 0; j < 16; j++) hr[j] = 0.f;
    for (int c = 0; c < NCHUNK; c++) {
        size_t base = ((size_t)(bh*NCHUNK + c)*HD + p)*DSTATE + q*16;
        #pragma unroll
        for (int j = 0; j < 16; j += 4)
            *(float4*)&g_hini[base + j] = make_float4(hr[j], hr[j+1], hr[j+2], hr[j+3]);
        float P = expf(A * g_sdt[bh*NCHUNK + c]);
        #pragma unroll
        for (int j = 0; j < 16; j += 4) {
            float4 hl = *(const float4*)&g_hloc[base + j];
            hr[j]   = fmaf(P, hr[j],   hl.x);
            hr[j+1] = fmaf(P, hr[j+1], hl.y);
            hr[j+2] = fmaf(P, hr[j+2], hl.z);
            hr[j+3] = fmaf(P, hr[j+3], hl.w);
        }
    }
}

__global__ __launch_bounds__(64)
void scan3_kernel(const float* __restrict__ A_log,
                  const float* __restrict__ D_param) {
    int chunk = blockIdx.x;
    int bh    = blockIdx.y;
    int b = bh >> 5, h = bh & 31;
    int p = threadIdx.x;
    float A  = -expf(A_log[h]);
    float Dp = D_param[h];
    unsigned long long hs2[DSTATE/2];
    {
        size_t base = ((size_t)(bh*NCHUNK + chunk)*HD + p)*DSTATE;
        #pragma unroll
        for (int n = 0; n < DSTATE; n += 4) {
            float4 hv = *(const float4*)&g_hini[base + n];
            PK2(hs2[n/2],   hv.x, hv.y);
            PK2(hs2[n/2+1], hv.z, hv.w);
        }
    }

    __shared__ float Bsm[8][DSTATE];
    __shared__ float Csm[8][DSTATE];
    __shared__ float dts[8];
    const int xcol = h*HD + p;
    int rbase0 = b*LL + chunk*LC;

    for (int t0 = 0; t0 < LC; t0 += 8) {
        #pragma unroll
        for (int s = 0; s < 8; s++) {
            size_t rb = (size_t)(rbase0 + t0 + s) * CONVD;
            Bsm[s][p] = g_xbc[rb + DI + p];
            Csm[s][p] = g_xbc[rb + DI + DSTATE + p];
        }
        if (p < 8) dts[p] = g_dt[(size_t)(rbase0 + t0 + p)*NH + h];
        __syncthreads();
        #pragma unroll
        for (int s = 0; s < 8; s++) {
            int row   = rbase0 + t0 + s;
            float dtv = dts[s];
            float a   = expf(dtv * A);
            float xv  = g_xbc[(size_t)row*CONVD + xcol];
            float dtx = dtv * xv;
            unsigned long long a2, dtx2, acc2 = 0ull;
            PK2(a2, a, a);
            PK2(dtx2, dtx, dtx);
            #pragma unroll
            for (int n = 0; n < DSTATE; n += 4) {
                float4 Bv = *(const float4*)&Bsm[s][n];
                float4 Cv = *(const float4*)&Csm[s][n];
                unsigned long long b01, b23, c01, c23, t01, t23;
                PK2(b01, Bv.x, Bv.y); PK2(b23, Bv.z, Bv.w);
                PK2(c01, Cv.x, Cv.y); PK2(c23, Cv.z, Cv.w);
                MUL2(t01, dtx2, b01);
                MUL2(t23, dtx2, b23);
                FMA2(hs2[n/2],   a2, hs2[n/2],   t01);
                FMA2(hs2[n/2+1], a2, hs2[n/2+1], t23);
                FMA2(acc2, hs2[n/2],   c01, acc2);
                FMA2(acc2, hs2[n/2+1], c23, acc2);
            }
            float alo, ahi;
            UPK2(alo, ahi, acc2);
            g_y[(size_t)row*DI + xcol] = __float2half_rn(alo + ahi + Dp*xv);
        }
        __syncthreads();
    }
}

// ---------------- y = rmsnorm(y * silu(z)) * norm_w (vectorized) ----------
__global__ void gate_rms_kernel(const float* __restrict__ norm_w) {
    size_t row = blockIdx.x;
    int c0 = threadIdx.x * 8;
    float zz[8];
    *(float4*)&zz[0] = *(const float4*)&g_zx[row*DIP + c0];
    *(float4*)&zz[4] = *(const float4*)&g_zx[row*DIP + c0 + 4];
    uint4 yu = *(const uint4*)&g_y[row*DI + c0];
    __half2 yh[4];
    yh[0] = *(__half2*)&yu.x; yh[1] = *(__half2*)&yu.y;
    yh[2] = *(__half2*)&yu.z; yh[3] = *(__half2*)&yu.w;
    float vals[8];
    float ss = 0.f;
    #pragma unroll
    for (int i = 0; i < 8; i++) {
        float z  = zz[i];
        float yv = (i & 1) ? __high2float(yh[i>>1]) : __low2float(yh[i>>1]);
        float gg = yv * (z / (1.0f + expf(-z)));
        vals[i] = gg;
        ss += gg*gg;
    }
    float ms = block_reduce_sum(ss) * (1.0f/DI);
    float r  = rsqrtf(ms + 1e-5f);
    float ww[8];
    *(float4*)&ww[0] = *(const float4*)&norm_w[c0];
    *(float4*)&ww[4] = *(const float4*)&norm_w[c0 + 4];
    uint4 o;
    __half2 oh[4];
    #pragma unroll
    for (int i = 0; i < 4; i++)
        oh[i] = __floats2half2_rn(vals[2*i] * r * ww[2*i], vals[2*i+1] * r * ww[2*i+1]);
    o.x = *(uint32_t*)&oh[0]; o.y = *(uint32_t*)&oh[1];
    o.z = *(uint32_t*)&oh[2]; o.w = *(uint32_t*)&oh[3];
    *(uint4*)&g_y[row*DI + c0] = o;
}

// ---------------- host launch ----------------
extern "C" void kernel_launch(void* const* d_in, const int* in_sizes, int n_in,
                              void* d_out, int out_size)
{
    const float* x         = (const float*)d_in[0];
    const float* ln1_w     = (const float*)d_in[1];
    const float* ln1_b     = (const float*)d_in[2];
    const float* ln2_w     = (const float*)d_in[3];
    const float* ln2_b     = (const float*)d_in[4];
    const float* in_proj_w = (const float*)d_in[5];
    const float* conv_w    = (const float*)d_in[6];
    const float* conv_b    = (const float*)d_in[7];
    const float* dt_bias   = (const float*)d_in[8];
    const float* A_log     = (const float*)d_in[9];
    const float* D_param   = (const float*)d_in[10];
    const float* norm_w    = (const float*)d_in[11];
    const float* out_proj_w= (const float*)d_in[12];
    const float* fc_w      = (const float*)d_in[13];
    const float* fc_b      = (const float*)d_in[14];
    const float* proj_w    = (const float*)d_in[15];
    const float* proj_b    = (const float*)d_in[16];
    float* out = (float*)d_out;

    __half *p_ln1, *p_y, *p_ln2, *p_mlp, *p_wh;
    float  *p_zx, *p_x2;
    cudaGetSymbolAddress((void**)&p_ln1, g_ln1);
    cudaGetSymbolAddress((void**)&p_zx,  g_zx);
    cudaGetSymbolAddress((void**)&p_y,   g_y);
    cudaGetSymbolAddress((void**)&p_x2,  g_x2);
    cudaGetSymbolAddress((void**)&p_ln2, g_ln2);
    cudaGetSymbolAddress((void**)&p_mlp, g_mlp);
    cudaGetSymbolAddress((void**)&p_wh,  g_wh);

    cudaFuncSetAttribute(tc_gemm<0>, cudaFuncAttributeMaxDynamicSharedMemorySize, GEMM_DYNSMEM);
    cudaFuncSetAttribute(tc_gemm<1>, cudaFuncAttributeMaxDynamicSharedMemorySize, GEMM_DYNSMEM);
    cudaFuncSetAttribute(tc_gemm<2>, cudaFuncAttributeMaxDynamicSharedMemorySize, GEMM_DYNSMEM);
    cudaFuncSetAttribute(tc_gemm<3>, cudaFuncAttributeMaxDynamicSharedMemorySize, GEMM_DYNSMEM);

    // 0. fp16-convert all weights (one launch)
    cvtw_all_kernel<<<(N4_TOTAL + 255)/256, 256>>>(
        (const float4*)in_proj_w, (const float4*)out_proj_w,
        (const float4*)fc_w, (const float4*)proj_w, (uint2*)p_wh);

    // 1. LN1 (half out)
    ln_kernel<<<MM, 256>>>(x, ln1_w, ln1_b, p_ln1);
    // 2. in_proj -> g_zx (f32)
    {
        dim3 grid((DIP + 127)/128, MM/128);
        tc_gemm<0><<<grid, 128, GEMM_DYNSMEM>>>(p_ln1, p_wh + WOFF_INPROJ,
                                                nullptr, nullptr, p_zx, MM, DIP, DM);
    }
    // 3+4. conv + silu + dt softplus (fused, one launch)
    conv_dt_kernel<<<(NCONV4 + NDT4 + 255)/256, 256>>>(conv_w, conv_b, dt_bias);
    // 5. chunked SSM scan
    {
        dim3 gs(NCHUNK, BB*NH);
        scan1_kernel<<<gs, 64>>>(A_log);
        scan2_kernel<<<BB*NH, 256>>>(A_log);
        scan3_kernel<<<gs, 64>>>(A_log, D_param);
    }
    // 6. gate + rmsnorm (half in/out)
    gate_rms_kernel<<<MM, 256>>>(norm_w);
    // 7. out_proj + residual(x) -> g_x2 (f32)
    {
        dim3 grid(DM/128, MM/128);
        tc_gemm<2><<<grid, 128, GEMM_DYNSMEM>>>(p_y, p_wh + WOFF_OUTPROJ,
                                                nullptr, x, p_x2, MM, DM, DI);
    }
    // 8. LN2 (half out)
    ln_kernel<<<MM, 256>>>(p_x2, ln2_w, ln2_b, p_ln2);
    // 9. fc + bias + gelu -> g_mlp (half out)
    {
        dim3 grid(DFF/128, MM/128);
        tc_gemm<1><<<grid, 128, GEMM_DYNSMEM>>>(p_ln2, p_wh + WOFF_FC,
                                                fc_b, nullptr, p_mlp, MM, DFF, DM);
    }
    // 10. proj + bias + residual(g_x2) -> out (f32)
    {
        dim3 grid(DM/128, MM/128);
        tc_gemm<3><<<grid, 128, GEMM_DYNSMEM>>>(p_mlp, p_wh + WOFF_PROJ,
                                                proj_b, p_x2, out, MM, DM, DFF);
    }
}

// round 17
// speedup vs baseline: 1.7107x; 1.0334x over previous
#include <cuda_runtime.h>
#include <cuda_fp16.h>
#include <cstdint>
#include <math.h>

// Problem constants
#define BB      4
#define LL      4096
#define DM      1024
#define DI      2048
#define DSTATE  64
#define HD      64
#define NH      32
#define CONVD   2176        // DI + 2*DSTATE
#define DIP     4256        // 2*DI + 2*DSTATE + NH
#define DFF     4096
#define MM      (BB*LL)     // 16384 rows
#define NCHUNK  16
#define LC      256         // LL / NCHUNK

// ---------------- scratch (static device globals; no allocs allowed) --------
__device__ __half g_ln1[MM*DM];
__device__ float  g_zx [MM*DIP];
__device__ float  g_xbc[MM*CONVD];
__device__ float  g_dt [MM*NH];
__device__ __half g_y  [MM*DI];
__device__ float  g_x2 [MM*DM];
__device__ __half g_ln2[MM*DM];
__device__ __half g_mlp[MM*DFF];
// chunked-scan buffers
__device__ float  g_hloc[BB*NH*NCHUNK*HD*DSTATE];
__device__ float  g_hini[BB*NH*NCHUNK*HD*DSTATE];
__device__ float  g_sdt [BB*NH*NCHUNK];
// fp16 weights (contiguous regions)
#define WOFF_INPROJ  0
#define WOFF_OUTPROJ (DIP*DM)
#define WOFF_FC      (WOFF_OUTPROJ + DM*DI)
#define WOFF_PROJ    (WOFF_FC + DFF*DM)
#define WTOTAL       (WOFF_PROJ + DM*DFF)
__device__ __half g_wh[WTOTAL];

// =================== helpers ===================
__device__ __forceinline__ void cp16(uint32_t dst, const void* src, uint32_t sz){
    asm volatile("cp.async.cg.shared.global [%0], [%1], 16, %2;" :: "r"(dst), "l"(src), "r"(sz));
}
__device__ __forceinline__ uint32_t smem_u32(const void* p){
    uint32_t a;
    asm("{ .reg .u64 t; cvta.to.shared.u64 t, %1; cvt.u32.u64 %0, t; }" : "=r"(a) : "l"(p));
    return a;
}
__device__ __forceinline__ void mma16816(float c[4], const uint32_t a[4], const uint32_t b[2]){
    asm volatile("mma.sync.aligned.m16n8k16.row.col.f32.f16.f16.f32 "
        "{%0,%1,%2,%3}, {%4,%5,%6,%7}, {%8,%9}, {%0,%1,%2,%3};"
        : "+f"(c[0]), "+f"(c[1]), "+f"(c[2]), "+f"(c[3])
        : "r"(a[0]), "r"(a[1]), "r"(a[2]), "r"(a[3]), "r"(b[0]), "r"(b[1]));
}
#define LDSM4(r0,r1,r2,r3,addr) \
    asm volatile("ldmatrix.sync.aligned.m8n8.x4.shared.b16 {%0,%1,%2,%3}, [%4];" \
        : "=r"(r0), "=r"(r1), "=r"(r2), "=r"(r3) : "r"(addr))
// packed f32x2 (Blackwell FFMA2 path)
#define PK2(out, lo, hi)  asm("mov.b64 %0, {%1, %2};" : "=l"(out) : "f"(lo), "f"(hi))
#define UPK2(lo, hi, in)  asm("mov.b64 {%0, %1}, %2;" : "=f"(lo), "=f"(hi) : "l"(in))
#define MUL2(d, a, b)     asm("mul.rn.f32x2 %0, %1, %2;" : "=l"(d) : "l"(a), "l"(b))
#define FMA2(d, a, b, c)  asm("fma.rn.f32x2 %0, %1, %2, %3;" : "=l"(d) : "l"(a), "l"(b), "l"(c))

// =================== fp16 mma.sync GEMM (R14 config: 3-stage, dist 2) ======
#define GPITCH 20
#define GROWB  (GPITCH*4)                        // 80 bytes per row
#define GSTAGE_U32 (2*128*GPITCH)
#define GSTAGE_BYTES (GSTAGE_U32*4)              // 20480
#define GSTAGES 3
#define GEMM_DYNSMEM (GSTAGES*GSTAGE_BYTES)      // 61440

template<int EPI>
__global__ __launch_bounds__(128, 2)
void tc_gemm(const __half* __restrict__ Ap, const __half* __restrict__ Wp,
             const float* __restrict__ bias, const float* __restrict__ resid,
             void* __restrict__ Cv, int M, int N, int K)
{
    extern __shared__ uint32_t smu[];
    uint32_t smem_base = smem_u32(smu);
    int tid  = threadIdx.x;
    int wid  = tid >> 5;
    int lane = tid & 31;
    int g    = lane >> 2;
    int t4   = lane & 3;
    int wm   = (wid & 1) * 64;
    int wn   = (wid >> 1) * 64;

    int m0 = blockIdx.y * 128;
    int n0 = blockIdx.x * 128;
    int NC = K >> 5;

    uint32_t a_off = (uint32_t)((wm + (lane & 7) + ((lane >> 3) & 1) * 8) * GROWB
                                + (lane >> 4) * 16);
    uint32_t b_off = (uint32_t)((wn + (lane & 7) + (lane >> 4) * 8) * GROWB
                                + ((lane >> 3) & 1) * 16);

    float acc[4][8][4];
    #pragma unroll
    for (int mi = 0; mi < 4; mi++)
        #pragma unroll
        for (int ni = 0; ni < 8; ni++)
            #pragma unroll
            for (int r = 0; r < 4; r++) acc[mi][ni][r] = 0.f;

    auto load_chunk = [&](int c){
        uint32_t sb = smem_base + (uint32_t)(c % GSTAGES) * GSTAGE_BYTES;
        int k0 = c << 5;
        #pragma unroll
        for (int i = 0; i < 4; i++) {
            int gr = i*128 + tid;
            int r = gr >> 2, c16 = gr & 3;
            cp16(sb + (uint32_t)(r*GROWB + c16*16),
                 Ap + (size_t)(m0 + r)*K + k0 + c16*8, 16u);
        }
        #pragma unroll
        for (int i = 0; i < 4; i++) {
            int gr = i*128 + tid;
            int r = gr >> 2, c16 = gr & 3;
            int nr = n0 + r;
            uint32_t sz = (nr < N) ? 16u : 0u;
            cp16(sb + (uint32_t)(128*GROWB) + (uint32_t)(r*GROWB + c16*16),
                 Wp + (size_t)(nr < N ? nr : 0)*K + k0 + c16*8, sz);
        }
        asm volatile("cp.async.commit_group;" ::: "memory");
    };

    load_chunk(0);
    if (NC > 1) load_chunk(1);

    for (int c = 0; c < NC; c++) {
        if (c + 1 < NC) { asm volatile("cp.async.wait_group 1;" ::: "memory"); }
        else            { asm volatile("cp.async.wait_group 0;" ::: "memory"); }
        __syncthreads();
        if (c + 2 < NC) load_chunk(c + 2);

        uint32_t sA = smem_base + (uint32_t)(c % GSTAGES) * GSTAGE_BYTES;
        uint32_t sB = sA + 128*GROWB;
        #pragma unroll
        for (int ks = 0; ks < 2; ks++) {
            uint32_t ks_off = (uint32_t)ks * 32;
            uint32_t a[4][4], b[8][2];
            #pragma unroll
            for (int mi = 0; mi < 4; mi++)
                LDSM4(a[mi][0], a[mi][1], a[mi][2], a[mi][3],
                      sA + a_off + (uint32_t)mi*(16*GROWB) + ks_off);
            #pragma unroll
            for (int pr = 0; pr < 4; pr++)
                LDSM4(b[2*pr][0], b[2*pr][1], b[2*pr+1][0], b[2*pr+1][1],
                      sB + b_off + (uint32_t)pr*(16*GROWB) + ks_off);
            #pragma unroll
            for (int mi = 0; mi < 4; mi++)
                #pragma unroll
                for (int ni = 0; ni < 8; ni++)
                    mma16816(acc[mi][ni], a[mi], b[ni]);
        }
    }

    float*  Cf = (float*)Cv;
    __half* Ch = (__half*)Cv;
    #pragma unroll
    for (int mi = 0; mi < 4; mi++) {
        int r0 = m0 + wm + mi*16 + g;
        #pragma unroll
        for (int ni = 0; ni < 8; ni++) {
            int cc = n0 + wn + ni*8 + t4*2;
            #pragma unroll
            for (int half_ = 0; half_ < 2; half_++) {
                int row = r0 + half_*8;
                float v0 = acc[mi][ni][half_*2 + 0];
                float v1 = acc[mi][ni][half_*2 + 1];
                if (cc + 1 < N) {
                    if (EPI == 1) {
                        v0 += bias[cc];   v1 += bias[cc+1];
                        v0 = 0.5f*v0*(1.0f + erff(v0*0.70710678118654752f));
                        v1 = 0.5f*v1*(1.0f + erff(v1*0.70710678118654752f));
                        *(__half2*)&Ch[(size_t)row*N + cc] = __floats2half2_rn(v0, v1);
                    } else {
                        if (EPI == 2) { v0 += resid[(size_t)row*N + cc];
                                        v1 += resid[(size_t)row*N + cc + 1]; }
                        if (EPI == 3) { v0 += bias[cc]   + resid[(size_t)row*N + cc];
                                        v1 += bias[cc+1] + resid[(size_t)row*N + cc + 1]; }
                        *(float2*)&Cf[(size_t)row*N + cc] = make_float2(v0, v1);
                    }
                } else if (cc < N) {
                    float v = v0;
                    if (EPI == 1) {
                        v += bias[cc];
                        v = 0.5f*v*(1.0f + erff(v*0.70710678118654752f));
                        Ch[(size_t)row*N + cc] = __float2half_rn(v);
                    } else {
                        if (EPI == 2) v += resid[(size_t)row*N + cc];
                        if (EPI == 3) v += bias[cc] + resid[(size_t)row*N + cc];
                        Cf[(size_t)row*N + cc] = v;
                    }
                }
            }
        }
    }
}

// =================== block reduction ===================
__device__ __forceinline__ float block_reduce_sum(float v) {
    __shared__ float sm[32];
    __shared__ float total;
    int lane = threadIdx.x & 31;
    int wid  = threadIdx.x >> 5;
    #pragma unroll
    for (int o = 16; o > 0; o >>= 1) v += __shfl_xor_sync(0xffffffffu, v, o);
    if (lane == 0) sm[wid] = v;
    __syncthreads();
    int nw = blockDim.x >> 5;
    v = (threadIdx.x < nw) ? sm[threadIdx.x] : 0.0f;
    if (wid == 0) {
        #pragma unroll
        for (int o = 16; o > 0; o >>= 1) v += __shfl_xor_sync(0xffffffffu, v, o);
        if (lane == 0) total = v;
    }
    __syncthreads();
    float r = total;
    __syncthreads();
    return r;
}

// ---------------- layernorm (float4 in, half out) ----------------
__global__ void ln_kernel(const float* __restrict__ x,
                          const float* __restrict__ w,
                          const float* __restrict__ b,
                          __half* __restrict__ out) {
    size_t base = (size_t)blockIdx.x * DM;
    int c0 = threadIdx.x * 4;
    float4 v = *(const float4*)&x[base + c0];
    float s = v.x + v.y + v.z + v.w;
    float mean = block_reduce_sum(s) * (1.0f/DM);
    float dx = v.x-mean, dy = v.y-mean, dz = v.z-mean, dw = v.w-mean;
    float var = block_reduce_sum(dx*dx + dy*dy + dz*dz + dw*dw) * (1.0f/DM);
    float rstd = rsqrtf(var + 1e-5f);
    float4 wv = *(const float4*)&w[c0];
    float4 bv = *(const float4*)&b[c0];
    __half2 o0 = __floats2half2_rn(dx*rstd*wv.x + bv.x, dy*rstd*wv.y + bv.y);
    __half2 o1 = __floats2half2_rn(dz*rstd*wv.z + bv.z, dw*rstd*wv.w + bv.w);
    uint2 o; o.x = *(uint32_t*)&o0; o.y = *(uint32_t*)&o1;
    *(uint2*)&out[base + c0] = o;
}

// ---------------- merged fp16 weight conversion (one launch) --------------
#define N4_INPROJ  (DIP*DM/4)
#define N4_OUTPROJ (DM*DI/4)
#define N4_FC      (DFF*DM/4)
#define N4_PROJ    (DM*DFF/4)
#define N4_TOTAL   (N4_INPROJ + N4_OUTPROJ + N4_FC + N4_PROJ)
__global__ void cvtw_all_kernel(const float4* __restrict__ w0,
                                const float4* __restrict__ w1,
                                const float4* __restrict__ w2,
                                const float4* __restrict__ w3,
                                uint2* __restrict__ d) {
    int i = blockIdx.x * blockDim.x + threadIdx.x;
    if (i >= N4_TOTAL) return;
    float4 v;
    if      (i < N4_INPROJ)                        v = w0[i];
    else if (i < N4_INPROJ + N4_OUTPROJ)           v = w1[i - N4_INPROJ];
    else if (i < N4_INPROJ + N4_OUTPROJ + N4_FC)   v = w2[i - N4_INPROJ - N4_OUTPROJ];
    else                                           v = w3[i - N4_INPROJ - N4_OUTPROJ - N4_FC];
    __half2 h0 = __floats2half2_rn(v.x, v.y);
    __half2 h1 = __floats2half2_rn(v.z, v.w);
    uint2 o; o.x = *(uint32_t*)&h0; o.y = *(uint32_t*)&h1;
    d[i] = o;
}

// ---------------- conv(4)+silu over 4 time-steps/thread + fused dt --------
// Conv range: each thread computes 4 consecutive rows (time steps) for its
// 4-channel group; loads the 7 overlapping taps once (2.3x less L1 traffic).
// dt range: softplus(dt_raw + dt_bias), 4 heads per thread.
#define NCONVT ((MM/4)*(CONVD/4))
#define NDT4   (MM*(NH/4))
__global__ void conv_dt_kernel(const float* __restrict__ conv_w,
                               const float* __restrict__ conv_b,
                               const float* __restrict__ dt_bias) {
    int idx = blockIdx.x * blockDim.x + threadIdx.x;
    if (idx < NCONVT) {
        int c4   = (idx % (CONVD/4)) * 4;
        int rowg = idx / (CONVD/4);
        int row0 = rowg * 4;              // LL%4==0 -> no batch straddle
        int l0   = row0 & (LL-1);
        float4 bias4 = *(const float4*)&conv_b[c4];
        float4 w0 = *(const float4*)&conv_w[(c4+0)*4];
        float4 w1 = *(const float4*)&conv_w[(c4+1)*4];
        float4 w2 = *(const float4*)&conv_w[(c4+2)*4];
        float4 w3 = *(const float4*)&conv_w[(c4+3)*4];
        float wk0[4] = {w0.x, w0.y, w0.z, w0.w};
        float wk1[4] = {w1.x, w1.y, w1.z, w1.w};
        float wk2[4] = {w2.x, w2.y, w2.z, w2.w};
        float wk3[4] = {w3.x, w3.y, w3.z, w3.w};
        float4 xv[7];
        #pragma unroll
        for (int k = 0; k < 7; k++) {
            int ls = l0 - 3 + k;
            if (ls >= 0)
                xv[k] = *(const float4*)&g_zx[(size_t)(row0-3+k)*DIP + DI + c4];
            else
                xv[k] = make_float4(0.f, 0.f, 0.f, 0.f);
        }
        #pragma unroll
        for (int s = 0; s < 4; s++) {
            float4 acc = bias4;
            #pragma unroll
            for (int k = 0; k < 4; k++) {
                float4 x = xv[s + k];
                acc.x = fmaf(wk0[k], x.x, acc.x);
                acc.y = fmaf(wk1[k], x.y, acc.y);
                acc.z = fmaf(wk2[k], x.z, acc.z);
                acc.w = fmaf(wk3[k], x.w, acc.w);
            }
            acc.x /= (1.0f + expf(-acc.x));
            acc.y /= (1.0f + expf(-acc.y));
            acc.z /= (1.0f + expf(-acc.z));
            acc.w /= (1.0f + expf(-acc.w));
            *(float4*)&g_xbc[(size_t)(row0+s)*CONVD + c4] = acc;
        }
    } else if (idx < NCONVT + NDT4) {
        int j   = idx - NCONVT;
        int h4  = (j % (NH/4)) * 4;
        int row = j / (NH/4);
        float4 v = *(const float4*)&g_zx[(size_t)row*DIP + 2*DI + 2*DSTATE + h4];
        float4 bv = *(const float4*)&dt_bias[h4];
        v.x += bv.x; v.y += bv.y; v.z += bv.z; v.w += bv.w;
        v.x = (v.x > 20.0f) ? v.x : log1pf(expf(v.x));
        v.y = (v.y > 20.0f) ? v.y : log1pf(expf(v.y));
        v.z = (v.z > 20.0f) ? v.z : log1pf(expf(v.z));
        v.w = (v.w > 20.0f) ? v.w : log1pf(expf(v.w));
        *(float4*)&g_dt[(size_t)row*NH + h4] = v;
    }
}

// ---------------- chunked SSM scan ----------------
__global__ __launch_bounds__(64)
void scan1_kernel(const float* __restrict__ A_log) {
    int chunk = blockIdx.x;
    int bh    = blockIdx.y;
    int b = bh >> 5, h = bh & 31;
    int p = threadIdx.x;
    float A = -expf(A_log[h]);
    unsigned long long hs2[DSTATE/2];
    #pragma unroll
    for (int n = 0; n < DSTATE/2; n++) hs2[n] = 0ull;
    float sdt = 0.f;

    __shared__ float Bsm[8][DSTATE];
    __shared__ float dts[8];
    const int xcol = h*HD + p;
    int rbase0 = b*LL + chunk*LC;

    for (int t0 = 0; t0 < LC; t0 += 8) {
        #pragma unroll
        for (int s = 0; s < 8; s++)
            Bsm[s][p] = g_xbc[(size_t)(rbase0 + t0 + s)*CONVD + DI + p];
        if (p < 8) dts[p] = g_dt[(size_t)(rbase0 + t0 + p)*NH + h];
        __syncthreads();
        #pragma unroll
        for (int s = 0; s < 8; s++) {
            int row   = rbase0 + t0 + s;
            float dtv = dts[s];
            sdt += dtv;
            float a   = expf(dtv * A);
            float xv  = g_xbc[(size_t)row*CONVD + xcol];
            float dtx = dtv * xv;
            unsigned long long a2, dtx2;
            PK2(a2, a, a);
            PK2(dtx2, dtx, dtx);
            #pragma unroll
            for (int n = 0; n < DSTATE; n += 4) {
                float4 Bv = *(const float4*)&Bsm[s][n];
                unsigned long long b01, b23, t01, t23;
                PK2(b01, Bv.x, Bv.y); PK2(b23, Bv.z, Bv.w);
                MUL2(t01, dtx2, b01);
                MUL2(t23, dtx2, b23);
                FMA2(hs2[n/2],   a2, hs2[n/2],   t01);
                FMA2(hs2[n/2+1], a2, hs2[n/2+1], t23);
            }
        }
        __syncthreads();
    }
    size_t base = ((size_t)(bh*NCHUNK + chunk)*HD + p)*DSTATE;
    #pragma unroll
    for (int n = 0; n < DSTATE; n += 4) {
        float4 o;
        UPK2(o.x, o.y, hs2[n/2]);
        UPK2(o.z, o.w, hs2[n/2+1]);
        *(float4*)&g_hloc[base + n] = o;
    }
    if (p == 0) g_sdt[bh*NCHUNK + chunk] = sdt;
}

__global__ __launch_bounds__(256)
void scan2_kernel(const float* __restrict__ A_log) {
    int bh = blockIdx.x;
    int h  = bh & 31;
    float A = -expf(A_log[h]);
    int p = threadIdx.x & 63;
    int q = threadIdx.x >> 6;
    float hr[16];
    #pragma unroll
    for (int j = 0; j < 16; j++) hr[j] = 0.f;
    for (int c = 0; c < NCHUNK; c++) {
        size_t base = ((size_t)(bh*NCHUNK + c)*HD + p)*DSTATE + q*16;
        #pragma unroll
        for (int j = 0; j < 16; j += 4)
            *(float4*)&g_hini[base + j] = make_float4(hr[j], hr[j+1], hr[j+2], hr[j+3]);
        float P = expf(A * g_sdt[bh*NCHUNK + c]);
        #pragma unroll
        for (int j = 0; j < 16; j += 4) {
            float4 hl = *(const float4*)&g_hloc[base + j];
            hr[j]   = fmaf(P, hr[j],   hl.x);
            hr[j+1] = fmaf(P, hr[j+1], hl.y);
            hr[j+2] = fmaf(P, hr[j+2], hl.z);
            hr[j+3] = fmaf(P, hr[j+3], hl.w);
        }
    }
}

__global__ __launch_bounds__(64)
void scan3_kernel(const float* __restrict__ A_log,
                  const float* __restrict__ D_param) {
    int chunk = blockIdx.x;
    int bh    = blockIdx.y;
    int b = bh >> 5, h = bh & 31;
    int p = threadIdx.x;
    float A  = -expf(A_log[h]);
    float Dp = D_param[h];
    unsigned long long hs2[DSTATE/2];
    {
        size_t base = ((size_t)(bh*NCHUNK + chunk)*HD + p)*DSTATE;
        #pragma unroll
        for (int n = 0; n < DSTATE; n += 4) {
            float4 hv = *(const float4*)&g_hini[base + n];
            PK2(hs2[n/2],   hv.x, hv.y);
            PK2(hs2[n/2+1], hv.z, hv.w);
        }
    }

    __shared__ float Bsm[8][DSTATE];
    __shared__ float Csm[8][DSTATE];
    __shared__ float dts[8];
    const int xcol = h*HD + p;
    int rbase0 = b*LL + chunk*LC;

    for (int t0 = 0; t0 < LC; t0 += 8) {
        #pragma unroll
        for (int s = 0; s < 8; s++) {
            size_t rb = (size_t)(rbase0 + t0 + s) * CONVD;
            Bsm[s][p] = g_xbc[rb + DI + p];
            Csm[s][p] = g_xbc[rb + DI + DSTATE + p];
        }
        if (p < 8) dts[p] = g_dt[(size_t)(rbase0 + t0 + p)*NH + h];
        __syncthreads();
        #pragma unroll
        for (int s = 0; s < 8; s++) {
            int row   = rbase0 + t0 + s;
            float dtv = dts[s];
            float a   = expf(dtv * A);
            float xv  = g_xbc[(size_t)row*CONVD + xcol];
            float dtx = dtv * xv;
            unsigned long long a2, dtx2, acc2 = 0ull;
            PK2(a2, a, a);
            PK2(dtx2, dtx, dtx);
            #pragma unroll
            for (int n = 0; n < DSTATE; n += 4) {
                float4 Bv = *(const float4*)&Bsm[s][n];
                float4 Cv = *(const float4*)&Csm[s][n];
                unsigned long long b01, b23, c01, c23, t01, t23;
                PK2(b01, Bv.x, Bv.y); PK2(b23, Bv.z, Bv.w);
                PK2(c01, Cv.x, Cv.y); PK2(c23, Cv.z, Cv.w);
                MUL2(t01, dtx2, b01);
                MUL2(t23, dtx2, b23);
                FMA2(hs2[n/2],   a2, hs2[n/2],   t01);
                FMA2(hs2[n/2+1], a2, hs2[n/2+1], t23);
                FMA2(acc2, hs2[n/2],   c01, acc2);
                FMA2(acc2, hs2[n/2+1], c23, acc2);
            }
            float alo, ahi;
            UPK2(alo, ahi, acc2);
            g_y[(size_t)row*DI + xcol] = __float2half_rn(alo + ahi + Dp*xv);
        }
        __syncthreads();
    }
}

// ---------------- y = rmsnorm(y * silu(z)) * norm_w (vectorized) ----------
__global__ void gate_rms_kernel(const float* __restrict__ norm_w) {
    size_t row = blockIdx.x;
    int c0 = threadIdx.x * 8;
    float zz[8];
    *(float4*)&zz[0] = *(const float4*)&g_zx[row*DIP + c0];
    *(float4*)&zz[4] = *(const float4*)&g_zx[row*DIP + c0 + 4];
    uint4 yu = *(const uint4*)&g_y[row*DI + c0];
    __half2 yh[4];
    yh[0] = *(__half2*)&yu.x; yh[1] = *(__half2*)&yu.y;
    yh[2] = *(__half2*)&yu.z; yh[3] = *(__half2*)&yu.w;
    float vals[8];
    float ss = 0.f;
    #pragma unroll
    for (int i = 0; i < 8; i++) {
        float z  = zz[i];
        float yv = (i & 1) ? __high2float(yh[i>>1]) : __low2float(yh[i>>1]);
        float gg = yv * (z / (1.0f + expf(-z)));
        vals[i] = gg;
        ss += gg*gg;
    }
    float ms = block_reduce_sum(ss) * (1.0f/DI);
    float r  = rsqrtf(ms + 1e-5f);
    float ww[8];
    *(float4*)&ww[0] = *(const float4*)&norm_w[c0];
    *(float4*)&ww[4] = *(const float4*)&norm_w[c0 + 4];
    uint4 o;
    __half2 oh[4];
    #pragma unroll
    for (int i = 0; i < 4; i++)
        oh[i] = __floats2half2_rn(vals[2*i] * r * ww[2*i], vals[2*i+1] * r * ww[2*i+1]);
    o.x = *(uint32_t*)&oh[0]; o.y = *(uint32_t*)&oh[1];
    o.z = *(uint32_t*)&oh[2]; o.w = *(uint32_t*)&oh[3];
    *(uint4*)&g_y[row*DI + c0] = o;
}

// ---------------- host launch ----------------
extern "C" void kernel_launch(void* const* d_in, const int* in_sizes, int n_in,
                              void* d_out, int out_size)
{
    const float* x         = (const float*)d_in[0];
    const float* ln1_w     = (const float*)d_in[1];
    const float* ln1_b     = (const float*)d_in[2];
    const float* ln2_w     = (const float*)d_in[3];
    const float* ln2_b     = (const float*)d_in[4];
    const float* in_proj_w = (const float*)d_in[5];
    const float* conv_w    = (const float*)d_in[6];
    const float* conv_b    = (const float*)d_in[7];
    const float* dt_bias   = (const float*)d_in[8];
    const float* A_log     = (const float*)d_in[9];
    const float* D_param   = (const float*)d_in[10];
    const float* norm_w    = (const float*)d_in[11];
    const float* out_proj_w= (const float*)d_in[12];
    const float* fc_w      = (const float*)d_in[13];
    const float* fc_b      = (const float*)d_in[14];
    const float* proj_w    = (const float*)d_in[15];
    const float* proj_b    = (const float*)d_in[16];
    float* out = (float*)d_out;

    __half *p_ln1, *p_y, *p_ln2, *p_mlp, *p_wh;
    float  *p_zx, *p_x2;
    cudaGetSymbolAddress((void**)&p_ln1, g_ln1);
    cudaGetSymbolAddress((void**)&p_zx,  g_zx);
    cudaGetSymbolAddress((void**)&p_y,   g_y);
    cudaGetSymbolAddress((void**)&p_x2,  g_x2);
    cudaGetSymbolAddress((void**)&p_ln2, g_ln2);
    cudaGetSymbolAddress((void**)&p_mlp, g_mlp);
    cudaGetSymbolAddress((void**)&p_wh,  g_wh);

    cudaFuncSetAttribute(tc_gemm<0>, cudaFuncAttributeMaxDynamicSharedMemorySize, GEMM_DYNSMEM);
    cudaFuncSetAttribute(tc_gemm<1>, cudaFuncAttributeMaxDynamicSharedMemorySize, GEMM_DYNSMEM);
    cudaFuncSetAttribute(tc_gemm<2>, cudaFuncAttributeMaxDynamicSharedMemorySize, GEMM_DYNSMEM);
    cudaFuncSetAttribute(tc_gemm<3>, cudaFuncAttributeMaxDynamicSharedMemorySize, GEMM_DYNSMEM);

    // 0. fp16-convert all weights (one launch)
    cvtw_all_kernel<<<(N4_TOTAL + 255)/256, 256>>>(
        (const float4*)in_proj_w, (const float4*)out_proj_w,
        (const float4*)fc_w, (const float4*)proj_w, (uint2*)p_wh);

    // 1. LN1 (half out)
    ln_kernel<<<MM, 256>>>(x, ln1_w, ln1_b, p_ln1);
    // 2. in_proj -> g_zx (f32)
    {
        dim3 grid((DIP + 127)/128, MM/128);
        tc_gemm<0><<<grid, 128, GEMM_DYNSMEM>>>(p_ln1, p_wh + WOFF_INPROJ,
                                                nullptr, nullptr, p_zx, MM, DIP, DM);
    }
    // 3+4. conv + silu (4 timesteps/thread) + dt softplus (fused)
    conv_dt_kernel<<<(NCONVT + NDT4 + 255)/256, 256>>>(conv_w, conv_b, dt_bias);
    // 5. chunked SSM scan
    {
        dim3 gs(NCHUNK, BB*NH);
        scan1_kernel<<<gs, 64>>>(A_log);
        scan2_kernel<<<BB*NH, 256>>>(A_log);
        scan3_kernel<<<gs, 64>>>(A_log, D_param);
    }
    // 6. gate + rmsnorm (half in/out)
    gate_rms_kernel<<<MM, 256>>>(norm_w);
    // 7. out_proj + residual(x) -> g_x2 (f32)
    {
        dim3 grid(DM/128, MM/128);
        tc_gemm<2><<<grid, 128, GEMM_DYNSMEM>>>(p_y, p_wh + WOFF_OUTPROJ,
                                                nullptr, x, p_x2, MM, DM, DI);
    }
    // 8. LN2 (half out)
    ln_kernel<<<MM, 256>>>(p_x2, ln2_w, ln2_b, p_ln2);
    // 9. fc + bias + gelu -> g_mlp (half out)
    {
        dim3 grid(DFF/128, MM/128);
        tc_gemm<1><<<grid, 128, GEMM_DYNSMEM>>>(p_ln2, p_wh + WOFF_FC,
                                                fc_b, nullptr, p_mlp, MM, DFF, DM);
    }
    // 10. proj + bias + residual(g_x2) -> out (f32)
    {
        dim3 grid(DM/128, MM/128);
        tc_gemm<3><<<grid, 128, GEMM_DYNSMEM>>>(p_mlp, p_wh + WOFF_PROJ,
                                                proj_b, p_x2, out, MM, DM, DFF);
    }
}